// round 9
// baseline (speedup 1.0000x reference)
#include <cuda_runtime.h>
#include <cuda_bf16.h>
#include <cstdint>

// ---------------- problem constants ----------------
#define N_NODES 50000
#define N_EDGES 250000
#define M_PAD 50048           // 391 * 128
// dims: 300 -> 1024 -> 512 -> 256 -> 128 -> 2048

// ---------------- static device scratch ----------------
// NOTE: __device__ globals are zero-initialized at module load. The degree
// arrays (g_ideg/g_odeg) are consumed accumulatively by hist_kernel, so each
// graph replay re-zeroes them at the END (cleanup_kernel) -> every run starts
// from the same state.
__device__ __align__(256) float g_t[(size_t)N_NODES * 512];             // GEMM fp32 out (layers 2-4)
__device__ __align__(256) float g_y[(size_t)N_NODES * 128];             // layer-4 activation fp32
__device__ __align__(256) __nv_bfloat16 g_Ah0[(size_t)M_PAD * 1024];    // split A ping
__device__ __align__(256) __nv_bfloat16 g_Al0[(size_t)M_PAD * 1024];
__device__ __align__(256) __nv_bfloat16 g_Ah1[(size_t)M_PAD * 1024];    // split A pong
__device__ __align__(256) __nv_bfloat16 g_Al1[(size_t)M_PAD * 1024];
__device__ __align__(256) __nv_bfloat16 g_Wh[1277952];                  // all layers, hi plane
__device__ __align__(256) __nv_bfloat16 g_Wl[1277952];                  // all layers, lo plane
__device__ __align__(256) float g_dinv_out[N_NODES];
__device__ __align__(256) float g_dinv_in[N_NODES];
// CSC structures
__device__ __align__(256) int g_ideg[N_NODES];   // zero at entry (load-time / cleanup)
__device__ __align__(256) int g_odeg[N_NODES];   // zero at entry
__device__ __align__(256) int g_off[N_NODES + 4];
__device__ __align__(256) int g_cur[N_NODES];
__device__ __align__(256) int g_csc[N_EDGES];

// per-layer W plane offsets (bf16 elements)
#define WOFF0 0
#define WOFF1 327680
#define WOFF2 851968
#define WOFF3 983040
#define WOFF4 1015808

// ================= helpers =================
__device__ __forceinline__ uint32_t smem_u32(const void* p) {
    uint32_t a;
    asm("{ .reg .u64 t; cvta.to.shared.u64 t, %1; cvt.u32.u64 %0, t; }" : "=r"(a) : "l"(p));
    return a;
}

__device__ __forceinline__ void ldm_x4(uint32_t& r0, uint32_t& r1, uint32_t& r2, uint32_t& r3,
                                       uint32_t addr) {
    asm volatile("ldmatrix.sync.aligned.m8n8.x4.shared.b16 {%0,%1,%2,%3}, [%4];"
                 : "=r"(r0), "=r"(r1), "=r"(r2), "=r"(r3) : "r"(addr));
}

__device__ __forceinline__ void mma_bf16(float* d, const uint32_t* a, const uint32_t* b) {
    asm volatile("mma.sync.aligned.m16n8k16.row.col.f32.bf16.bf16.f32 "
                 "{%0,%1,%2,%3}, {%4,%5,%6,%7}, {%8,%9}, {%0,%1,%2,%3};"
                 : "+f"(d[0]), "+f"(d[1]), "+f"(d[2]), "+f"(d[3])
                 : "r"(a[0]), "r"(a[1]), "r"(a[2]), "r"(a[3]), "r"(b[0]), "r"(b[1]));
}

// fp32 -> bf16 hi/lo split, packed pair (low 16 bits = even-k element)
__device__ __forceinline__ void split2(float a, float b, uint32_t& hi, uint32_t& lo) {
    __nv_bfloat16 ah = __float2bfloat16(a);
    __nv_bfloat16 bh = __float2bfloat16(b);
    __nv_bfloat16 al = __float2bfloat16(a - __bfloat162float(ah));
    __nv_bfloat16 bl = __float2bfloat16(b - __bfloat162float(bh));
    hi = ((uint32_t)__bfloat16_as_ushort(bh) << 16) | (uint32_t)__bfloat16_as_ushort(ah);
    lo = ((uint32_t)__bfloat16_as_ushort(bl) << 16) | (uint32_t)__bfloat16_as_ushort(al);
}

// ================= pipelined bf16x3 mma.sync GEMM =================
// C = A @ Wt^T, A = Ah+Al [M_PAD, sA], Wt = Wh+Wl [N, sA] (k-major rows).
// Epilogue modes:
//  0: C[m][n] = d                         (fp32 t for gather_post)
//  1: A'(next) = split(leaky(d + bias[n]) * dout[m])   (stride sNext)
//  2: C[m][n] = d + bias[n]               (final output)
#define APAD 40                 // bf16 row stride in smem (80B)
#define TILE_B 10240            // 128*40*2 bytes per tile
#define STAGE_B 40960           // 4 tiles
#define SMEM_TOTAL_B 81920      // 2 stages

__global__ __launch_bounds__(256)
void gemm_mma(const __nv_bfloat16* __restrict__ Ah, const __nv_bfloat16* __restrict__ Al,
              const __nv_bfloat16* __restrict__ Wh, const __nv_bfloat16* __restrict__ Wl,
              float* __restrict__ C, int M, int N, int sA,
              int mode, const float* __restrict__ bias, const float* __restrict__ dout,
              __nv_bfloat16* __restrict__ oAh, __nv_bfloat16* __restrict__ oAl, int sNext) {
    extern __shared__ __nv_bfloat16 dsm[];
    const uint32_t sbase = smem_u32(dsm);

    const int tid = threadIdx.x, lane = tid & 31, wid = tid >> 5;
    const int bm = blockIdx.y * 128, bn = blockIdx.x * 128;
    const int wm = (wid >> 1) * 32, wn = (wid & 1) * 64;
    const int nkt = sA >> 5;

    const int g = lane >> 3, l8 = lane & 7;
    const uint32_t aoff = (uint32_t)(((g & 1) * 8 + l8) * APAD + (g >> 1) * 8);
    const uint32_t boff = (uint32_t)(((g >> 1) * 8 + l8) * APAD + (g & 1) * 8);

    auto load_stage = [&](int kt, int st) {
        const int k0 = kt << 5;
        #pragma unroll
        for (int it = 0; it < 8; it++) {
            const int idx = it * 256 + tid;
            const int t = idx >> 9, rc = idx & 511;
            const int r = rc >> 2, c = rc & 3;
            const __nv_bfloat16* gsrc;
            if (t == 0)      gsrc = Ah + (size_t)(bm + r) * sA + k0 + c * 8;
            else if (t == 1) gsrc = Al + (size_t)(bm + r) * sA + k0 + c * 8;
            else if (t == 2) gsrc = Wh + (size_t)(bn + r) * sA + k0 + c * 8;
            else             gsrc = Wl + (size_t)(bn + r) * sA + k0 + c * 8;
            const uint32_t d = sbase + st * STAGE_B + t * TILE_B + r * 80 + c * 16;
            asm volatile("cp.async.ca.shared.global [%0], [%1], 16;" :: "r"(d), "l"(gsrc));
        }
    };

    float acc[2][8][4] = {};

    load_stage(0, 0);
    asm volatile("cp.async.commit_group;" ::: "memory");

    for (int kt = 0; kt < nkt; kt++) {
        const int st = kt & 1;
        if (kt + 1 < nkt) {
            load_stage(kt + 1, st ^ 1);
            asm volatile("cp.async.commit_group;" ::: "memory");
            asm volatile("cp.async.wait_group 1;" ::: "memory");
        } else {
            asm volatile("cp.async.wait_group 0;" ::: "memory");
        }
        __syncthreads();

        const uint32_t sAh_u = sbase + st * STAGE_B;
        const uint32_t sAl_u = sAh_u + TILE_B;
        const uint32_t sBh_u = sAh_u + 2 * TILE_B;
        const uint32_t sBl_u = sAh_u + 3 * TILE_B;

        #pragma unroll
        for (int ks = 0; ks < 2; ks++) {
            uint32_t ah[2][4], al[2][4];
            #pragma unroll
            for (int mb = 0; mb < 2; mb++) {
                const uint32_t off = (aoff + (uint32_t)(wm + mb * 16) * APAD + ks * 16) * 2;
                ldm_x4(ah[mb][0], ah[mb][1], ah[mb][2], ah[mb][3], sAh_u + off);
                ldm_x4(al[mb][0], al[mb][1], al[mb][2], al[mb][3], sAl_u + off);
            }
            #pragma unroll
            for (int nbp = 0; nbp < 4; nbp++) {
                const uint32_t off = (boff + (uint32_t)(wn + nbp * 16) * APAD + ks * 16) * 2;
                uint32_t bh[4], bl[4];
                ldm_x4(bh[0], bh[1], bh[2], bh[3], sBh_u + off);
                ldm_x4(bl[0], bl[1], bl[2], bl[3], sBl_u + off);
                #pragma unroll
                for (int h = 0; h < 2; h++) {
                    #pragma unroll
                    for (int mb = 0; mb < 2; mb++) {
                        float* d = acc[mb][nbp * 2 + h];
                        mma_bf16(d, ah[mb], bh + h * 2);
                        mma_bf16(d, ah[mb], bl + h * 2);
                        mma_bf16(d, al[mb], bh + h * 2);
                    }
                }
            }
        }
        __syncthreads();
    }

    const int mrow = lane >> 2, ncol = (lane & 3) * 2;
    #pragma unroll
    for (int mb = 0; mb < 2; mb++) {
        const int m0 = bm + wm + mb * 16 + mrow;
        float dv0 = 0.f, dv1 = 0.f;
        if (mode == 1) {
            if (m0 < M) dv0 = dout[m0];
            if (m0 + 8 < M) dv1 = dout[m0 + 8];
        }
        #pragma unroll
        for (int nb = 0; nb < 8; nb++) {
            const float* d = acc[mb][nb];
            const int n = bn + wn + nb * 8 + ncol;
            if (mode == 0) {
                if (m0 < M)
                    *reinterpret_cast<float2*>(C + (size_t)m0 * N + n) = make_float2(d[0], d[1]);
                if (m0 + 8 < M)
                    *reinterpret_cast<float2*>(C + (size_t)(m0 + 8) * N + n) = make_float2(d[2], d[3]);
            } else if (mode == 2) {
                const float b0 = bias[n], b1 = bias[n + 1];
                if (m0 < M)
                    *reinterpret_cast<float2*>(C + (size_t)m0 * N + n) = make_float2(d[0] + b0, d[1] + b1);
                if (m0 + 8 < M)
                    *reinterpret_cast<float2*>(C + (size_t)(m0 + 8) * N + n) = make_float2(d[2] + b0, d[3] + b1);
            } else {
                const float b0 = bias[n], b1 = bias[n + 1];
                if (m0 < M) {
                    float v0 = d[0] + b0, v1 = d[1] + b1;
                    v0 = ((v0 < 0.f) ? 0.01f * v0 : v0) * dv0;
                    v1 = ((v1 < 0.f) ? 0.01f * v1 : v1) * dv0;
                    uint32_t hi, lo; split2(v0, v1, hi, lo);
                    *reinterpret_cast<uint32_t*>(oAh + (size_t)m0 * sNext + n) = hi;
                    *reinterpret_cast<uint32_t*>(oAl + (size_t)m0 * sNext + n) = lo;
                }
                if (m0 + 8 < M) {
                    float v0 = d[2] + b0, v1 = d[3] + b1;
                    v0 = ((v0 < 0.f) ? 0.01f * v0 : v0) * dv1;
                    v1 = ((v1 < 0.f) ? 0.01f * v1 : v1) * dv1;
                    uint32_t hi, lo; split2(v0, v1, hi, lo);
                    *reinterpret_cast<uint32_t*>(oAh + (size_t)(m0 + 8) * sNext + n) = hi;
                    *reinterpret_cast<uint32_t*>(oAl + (size_t)(m0 + 8) * sNext + n) = lo;
                }
            }
        }
    }
}

// ================= fused W prep: all 5 layers in one launch =================
// pair ranges per layer (uint32 pairs): L1 163840 | L2 262144 | L3 65536 | L4 16384 | L5 131072
__global__ void prep_w_all(const float* __restrict__ W0, const float* __restrict__ W1,
                           const float* __restrict__ W2, const float* __restrict__ W3,
                           const float* __restrict__ W4,
                           __nv_bfloat16* __restrict__ Wh, __nv_bfloat16* __restrict__ Wl) {
    const int starts[6] = {0, 163840, 425984, 491520, 507904, 638976};
    const int Ks[5]     = {300, 1024, 512, 256, 128};
    const int Ns[5]     = {1024, 512, 256, 128, 2048};
    const int Kpads[5]  = {320, 1024, 512, 256, 128};
    const int woffs[5]  = {WOFF0, WOFF1, WOFF2, WOFF3, WOFF4};
    const float* Ws[5]  = {W0, W1, W2, W3, W4};

    int idx = blockIdx.x * blockDim.x + threadIdx.x;
    int stride = gridDim.x * blockDim.x;
    for (; idx < 638976; idx += stride) {
        int l = 0;
        #pragma unroll
        for (int q = 1; q < 5; q++) if (idx >= starts[q]) l = q;
        const int p = idx - starts[l];
        const int Kp2 = Kpads[l] >> 1;
        const int n = p / Kp2, pk = p - n * Kp2;
        const int k = pk * 2;
        const int K = Ks[l], N = Ns[l];
        float w0 = 0.f, w1 = 0.f;
        if (k < K)     w0 = Ws[l][(size_t)k * N + n];
        if (k + 1 < K) w1 = Ws[l][(size_t)(k + 1) * N + n];
        uint32_t hi, lo; split2(w0, w1, hi, lo);
        ((uint32_t*)(Wh + woffs[l]))[p] = hi;
        ((uint32_t*)(Wl + woffs[l]))[p] = lo;
    }
}

// ================= CSC build =================
__global__ void hist_kernel(const int* __restrict__ src, const int* __restrict__ dst,
                            int* __restrict__ odeg, int* __restrict__ ideg, int nE) {
    int e = blockIdx.x * blockDim.x + threadIdx.x;
    if (e >= nE) return;
    int s = src[e], d = dst[e];
    if ((unsigned)s < N_NODES) atomicAdd(&odeg[s], 1);
    if ((unsigned)d < N_NODES) atomicAdd(&ideg[d], 1);
}

// single-block sequential scan over in-degrees + dinv computation (one launch)
__global__ __launch_bounds__(1024)
void scan_dinv_kernel(const int* __restrict__ ideg, const int* __restrict__ odeg,
                      int* __restrict__ off, int* __restrict__ cur,
                      float* __restrict__ dout, float* __restrict__ din) {
    __shared__ int sh[1024];
    __shared__ int carry;
    if (threadIdx.x == 0) carry = 0;
    __syncthreads();
    for (int base = 0; base < N_NODES; base += 1024) {
        const int i = base + threadIdx.x;
        const int v = (i < N_NODES) ? ideg[i] : 0;
        if (i < N_NODES) {
            dout[i] = rsqrtf(fmaxf((float)odeg[i], 1.0f));
            din[i]  = rsqrtf(fmaxf((float)v, 1.0f));
        }
        sh[threadIdx.x] = v;
        __syncthreads();
        #pragma unroll
        for (int s = 1; s < 1024; s <<= 1) {
            int add = (threadIdx.x >= s) ? sh[threadIdx.x - s] : 0;
            __syncthreads();
            sh[threadIdx.x] += add;
            __syncthreads();
        }
        if (i < N_NODES) {
            const int excl = sh[threadIdx.x] - v + carry;
            off[i] = excl;
            cur[i] = excl;
        }
        __syncthreads();
        if (threadIdx.x == 0) carry += sh[1023];
        __syncthreads();
    }
    if (threadIdx.x == 0) off[N_NODES] = carry;
}

__global__ void fill_kernel(const int* __restrict__ src, const int* __restrict__ dst,
                            int* __restrict__ cur, int* __restrict__ csc, int nE) {
    int e = blockIdx.x * blockDim.x + threadIdx.x;
    if (e >= nE) return;
    int s = src[e], d = dst[e];
    if ((unsigned)s >= N_NODES || (unsigned)d >= N_NODES) return;
    int pos = atomicAdd(&cur[d], 1);
    csc[pos] = s;
}

// restore degree arrays to zero for the next graph replay (runs LAST)
__global__ void cleanup_kernel(int* __restrict__ ideg, int* __restrict__ odeg) {
    int i = blockIdx.x * blockDim.x + threadIdx.x;
    if (i < N_NODES) { ideg[i] = 0; odeg[i] = 0; }
}

// ================= gather_pre: u = dinv_in ⊙ S (opt dout ⊙) y  -> split bf16 =================
__global__ __launch_bounds__(256)
void gather_pre(const float* __restrict__ y, const float* __restrict__ dout,
                const int* __restrict__ off, const int* __restrict__ csc,
                int K4, int Kpad4,
                __nv_bfloat16* __restrict__ Ah, __nv_bfloat16* __restrict__ Al, int sNext,
                const float* __restrict__ dinv_in) {
    const int node = blockIdx.x * 8 + (threadIdx.x >> 5);
    if (node >= N_NODES) return;
    const int lane = threadIdx.x & 31;
    const int beg = off[node], end = off[node + 1];
    const float di = dinv_in[node];
    const float4* y4 = (const float4*)y;

    for (int c = lane; c < Kpad4; c += 32) {
        float4 acc = make_float4(0.f, 0.f, 0.f, 0.f);
        if (c < K4) {
            for (int j = beg; j < end; j++) {
                const int s = csc[j];
                float4 v = y4[(size_t)s * K4 + c];
                const float sc = dout ? dout[s] : 1.0f;
                acc.x += v.x * sc; acc.y += v.y * sc; acc.z += v.z * sc; acc.w += v.w * sc;
            }
        }
        uint32_t h0, l0, h1, l1;
        split2(acc.x * di, acc.y * di, h0, l0);
        split2(acc.z * di, acc.w * di, h1, l1);
        const size_t eo = (size_t)node * sNext + c * 4;
        *reinterpret_cast<uint2*>(Ah + eo) = make_uint2(h0, h1);
        *reinterpret_cast<uint2*>(Al + eo) = make_uint2(l0, l1);
    }
}

// ================= gather_post: agg = S t; act = leaky(dinv_in⊙agg + b) ⊙ dinv_out =================
__global__ __launch_bounds__(256)
void gather_post(const float* __restrict__ t, const int* __restrict__ off,
                 const int* __restrict__ csc, int N4, int cpn,
                 __nv_bfloat16* __restrict__ Ah, __nv_bfloat16* __restrict__ Al, int sNext,
                 const float* __restrict__ bias, const float* __restrict__ dinv_in,
                 const float* __restrict__ dinv_out, float* __restrict__ outF) {
    const int gw = blockIdx.x * 8 + (threadIdx.x >> 5);
    const int lane = threadIdx.x & 31;
    const int node = gw / cpn, chunk = gw - node * cpn;
    if (node >= N_NODES) return;
    const int c = chunk * 32 + lane;

    const float4* t4 = (const float4*)t;
    const int beg = off[node], end = off[node + 1];
    float4 acc = make_float4(0.f, 0.f, 0.f, 0.f);
    for (int j = beg; j < end; j++) {
        const int s = csc[j];
        float4 v = t4[(size_t)s * N4 + c];
        acc.x += v.x; acc.y += v.y; acc.z += v.z; acc.w += v.w;
    }
    const float di = dinv_in[node];
    const float dv = dinv_out[node];
    const float4 b = ((const float4*)bias)[c];
    float v0 = fmaf(acc.x, di, b.x);
    float v1 = fmaf(acc.y, di, b.y);
    float v2 = fmaf(acc.z, di, b.z);
    float v3 = fmaf(acc.w, di, b.w);
    v0 = ((v0 < 0.f) ? 0.01f * v0 : v0) * dv;
    v1 = ((v1 < 0.f) ? 0.01f * v1 : v1) * dv;
    v2 = ((v2 < 0.f) ? 0.01f * v2 : v2) * dv;
    v3 = ((v3 < 0.f) ? 0.01f * v3 : v3) * dv;

    if (outF) {
        ((float4*)outF)[(size_t)node * N4 + c] = make_float4(v0, v1, v2, v3);
    } else {
        uint32_t h0, l0, h1, l1;
        split2(v0, v1, h0, l0);
        split2(v2, v3, h1, l1);
        const size_t eo = (size_t)node * sNext + c * 4;
        *reinterpret_cast<uint2*>(Ah + eo) = make_uint2(h0, h1);
        *reinterpret_cast<uint2*>(Al + eo) = make_uint2(l0, l1);
    }
}

// ================= launch =================
extern "C" void kernel_launch(void* const* d_in, const int* in_sizes, int n_in,
                              void* d_out, int out_size) {
    const float* x = (const float*)d_in[0];
    const int* ei = (const int*)d_in[1];   // int32 (JAX x64 disabled)
    const float* W[5] = {(const float*)d_in[2], (const float*)d_in[4], (const float*)d_in[6],
                         (const float*)d_in[8], (const float*)d_in[10]};
    const float* B[5] = {(const float*)d_in[3], (const float*)d_in[5], (const float*)d_in[7],
                         (const float*)d_in[9], (const float*)d_in[11]};

    const int M = N_NODES;
    const int nE = N_EDGES;
    const int* src = ei;
    const int* dstp = ei + nE;

    float *tP, *yP, *doutP, *dinP;
    __nv_bfloat16 *Ah0, *Al0, *Ah1, *Al1, *WhP, *WlP;
    int *idegP, *odegP, *offP, *curP, *cscP;
    cudaGetSymbolAddress((void**)&tP, g_t);
    cudaGetSymbolAddress((void**)&yP, g_y);
    cudaGetSymbolAddress((void**)&Ah0, g_Ah0);
    cudaGetSymbolAddress((void**)&Al0, g_Al0);
    cudaGetSymbolAddress((void**)&Ah1, g_Ah1);
    cudaGetSymbolAddress((void**)&Al1, g_Al1);
    cudaGetSymbolAddress((void**)&WhP, g_Wh);
    cudaGetSymbolAddress((void**)&WlP, g_Wl);
    cudaGetSymbolAddress((void**)&doutP, g_dinv_out);
    cudaGetSymbolAddress((void**)&dinP, g_dinv_in);
    cudaGetSymbolAddress((void**)&idegP, g_ideg);
    cudaGetSymbolAddress((void**)&odegP, g_odeg);
    cudaGetSymbolAddress((void**)&offP, g_off);
    cudaGetSymbolAddress((void**)&curP, g_cur);
    cudaGetSymbolAddress((void**)&cscP, g_csc);

    cudaFuncSetAttribute(gemm_mma, cudaFuncAttributeMaxDynamicSharedMemorySize, SMEM_TOTAL_B);

    // 1: degrees (g_ideg/g_odeg are zero: load-init on first call, cleanup on replays)
    hist_kernel<<<(nE + 255) / 256, 256>>>(src, dstp, odegP, idegP, nE);
    // 2: exclusive scan -> off/cur, plus dinv
    scan_dinv_kernel<<<1, 1024>>>(idegP, odegP, offP, curP, doutP, dinP);
    // 3: CSC fill
    fill_kernel<<<(nE + 255) / 256, 256>>>(src, dstp, curP, cscP, nE);
    // 4: layer-1 pre-aggregation (K=300 -> split A0, stride 320)
    gather_pre<<<(M + 7) / 8, 256>>>(x, doutP, offP, cscP, 75, 80, Ah0, Al0, 320, dinP);
    // 5: all weight planes
    prep_w_all<<<640, 256>>>(W[0], W[1], W[2], W[3], W[4], WhP, WlP);

    // 6: Layer 1 GEMM (K=320, N=1024) epilogue -> split A1   [ncu -s 5 lands here]
    {
        dim3 grid(1024 / 128, M_PAD / 128);
        gemm_mma<<<grid, 256, SMEM_TOTAL_B>>>(Ah0, Al0, WhP + WOFF0, WlP + WOFF0, nullptr,
                                              M, 1024, 320, 1, B[0], doutP, Ah1, Al1, 1024);
    }
    // 7-8: Layer 2 (K=1024, N=512)
    {
        dim3 grid(512 / 128, M_PAD / 128);
        gemm_mma<<<grid, 256, SMEM_TOTAL_B>>>(Ah1, Al1, WhP + WOFF1, WlP + WOFF1, tP,
                                              M, 512, 1024, 0, nullptr, nullptr, nullptr, nullptr, 0);
    }
    gather_post<<<(M * 4 + 7) / 8, 256>>>(tP, offP, cscP, 128, 4, Ah0, Al0, 512,
                                          B[1], dinP, doutP, nullptr);
    // 9-10: Layer 3 (K=512, N=256)
    {
        dim3 grid(256 / 128, M_PAD / 128);
        gemm_mma<<<grid, 256, SMEM_TOTAL_B>>>(Ah0, Al0, WhP + WOFF2, WlP + WOFF2, tP,
                                              M, 256, 512, 0, nullptr, nullptr, nullptr, nullptr, 0);
    }
    gather_post<<<(M * 2 + 7) / 8, 256>>>(tP, offP, cscP, 64, 2, Ah1, Al1, 256,
                                          B[2], dinP, doutP, nullptr);
    // 11-12: Layer 4 (K=256, N=128) -> fp32 y
    {
        dim3 grid(128 / 128, M_PAD / 128);
        gemm_mma<<<grid, 256, SMEM_TOTAL_B>>>(Ah1, Al1, WhP + WOFF3, WlP + WOFF3, tP,
                                              M, 128, 256, 0, nullptr, nullptr, nullptr, nullptr, 0);
    }
    gather_post<<<(M + 7) / 8, 256>>>(tP, offP, cscP, 32, 1, nullptr, nullptr, 0,
                                      B[3], dinP, doutP, yP);
    // 13-14: Layer 5 (aggregate-first, K=128, N=2048) -> d_out
    gather_pre<<<(M + 7) / 8, 256>>>(yP, nullptr, offP, cscP, 32, 32, Ah0, Al0, 128, dinP);
    {
        dim3 grid(2048 / 128, M_PAD / 128);
        gemm_mma<<<grid, 256, SMEM_TOTAL_B>>>(Ah0, Al0, WhP + WOFF4, WlP + WOFF4, (float*)d_out,
                                              M, 2048, 128, 2, B[4], nullptr, nullptr, nullptr, 0);
    }
    // 15: restore degree arrays for next replay
    cleanup_kernel<<<(M + 255) / 256, 256>>>(idegP, odegP);
}

// round 10
// speedup vs baseline: 1.0496x; 1.0496x over previous
#include <cuda_runtime.h>
#include <cuda_bf16.h>
#include <cstdint>

// ---------------- problem constants ----------------
#define N_NODES 50000
#define N_EDGES 250000
#define M_PAD 50048           // 391 * 128
// dims: 300 -> 1024 -> 512 -> 256 -> 128 -> 2048

// ---------------- static device scratch ----------------
// __device__ globals load zeroed; g_ideg/g_odeg are re-zeroed at the END of
// each replay (cleanup_kernel) so every graph replay starts from zero.
__device__ __align__(256) float g_t[(size_t)N_NODES * 512];             // GEMM fp32 out (layers 2-4)
__device__ __align__(256) float g_y[(size_t)N_NODES * 128];             // layer-4 activation fp32
__device__ __align__(256) __nv_bfloat16 g_Ah0[(size_t)M_PAD * 1024];    // split A ping
__device__ __align__(256) __nv_bfloat16 g_Al0[(size_t)M_PAD * 1024];
__device__ __align__(256) __nv_bfloat16 g_Ah1[(size_t)M_PAD * 1024];    // split A pong
__device__ __align__(256) __nv_bfloat16 g_Al1[(size_t)M_PAD * 1024];
__device__ __align__(256) __nv_bfloat16 g_Wh[1277952];                  // all layers, hi plane
__device__ __align__(256) __nv_bfloat16 g_Wl[1277952];                  // all layers, lo plane
__device__ __align__(256) float g_dinv_out[N_NODES];
__device__ __align__(256) float g_dinv_in[N_NODES];
// CSC structures
__device__ __align__(256) int g_ideg[N_NODES];   // zero at entry
__device__ __align__(256) int g_odeg[N_NODES];   // zero at entry
__device__ __align__(256) int g_off[N_NODES + 4];
__device__ __align__(256) int g_cur[N_NODES];
__device__ __align__(256) int g_csc[N_EDGES];
__device__ __align__(256) int g_bsum[128];

// per-layer W plane offsets (bf16 elements)
#define WOFF0 0
#define WOFF1 327680
#define WOFF2 851968
#define WOFF3 983040
#define WOFF4 1015808

// ================= helpers =================
__device__ __forceinline__ uint32_t smem_u32(const void* p) {
    uint32_t a;
    asm("{ .reg .u64 t; cvta.to.shared.u64 t, %1; cvt.u32.u64 %0, t; }" : "=r"(a) : "l"(p));
    return a;
}

__device__ __forceinline__ void ldm_x4(uint32_t& r0, uint32_t& r1, uint32_t& r2, uint32_t& r3,
                                       uint32_t addr) {
    asm volatile("ldmatrix.sync.aligned.m8n8.x4.shared.b16 {%0,%1,%2,%3}, [%4];"
                 : "=r"(r0), "=r"(r1), "=r"(r2), "=r"(r3) : "r"(addr));
}

__device__ __forceinline__ void mma_bf16(float* d, const uint32_t* a, const uint32_t* b) {
    asm volatile("mma.sync.aligned.m16n8k16.row.col.f32.bf16.bf16.f32 "
                 "{%0,%1,%2,%3}, {%4,%5,%6,%7}, {%8,%9}, {%0,%1,%2,%3};"
                 : "+f"(d[0]), "+f"(d[1]), "+f"(d[2]), "+f"(d[3])
                 : "r"(a[0]), "r"(a[1]), "r"(a[2]), "r"(a[3]), "r"(b[0]), "r"(b[1]));
}

// fp32 -> bf16 hi/lo split, packed pair (low 16 bits = even-k element)
__device__ __forceinline__ void split2(float a, float b, uint32_t& hi, uint32_t& lo) {
    __nv_bfloat16 ah = __float2bfloat16(a);
    __nv_bfloat16 bh = __float2bfloat16(b);
    __nv_bfloat16 al = __float2bfloat16(a - __bfloat162float(ah));
    __nv_bfloat16 bl = __float2bfloat16(b - __bfloat162float(bh));
    hi = ((uint32_t)__bfloat16_as_ushort(bh) << 16) | (uint32_t)__bfloat16_as_ushort(ah);
    lo = ((uint32_t)__bfloat16_as_ushort(bl) << 16) | (uint32_t)__bfloat16_as_ushort(al);
}

// ================= pipelined bf16x3 mma.sync GEMM =================
// C = A @ Wt^T, A = Ah+Al [M_PAD, sA], Wt = Wh+Wl [N, sA] (k-major rows).
// Epilogue modes:
//  0: C[m][n] = d                         (fp32 t for gather_post)
//  1: A'(next) = split(leaky(d + bias[n]) * dout[m])   (stride sNext)
//  2: C[m][n] = d + bias[n]               (final output)
#define APAD 40                 // bf16 row stride in smem (80B)
#define TILE_B 10240            // 128*40*2 bytes per tile
#define STAGE_B 40960           // 4 tiles
#define SMEM_TOTAL_B 81920      // 2 stages

__global__ __launch_bounds__(256)
void gemm_mma(const __nv_bfloat16* __restrict__ Ah, const __nv_bfloat16* __restrict__ Al,
              const __nv_bfloat16* __restrict__ Wh, const __nv_bfloat16* __restrict__ Wl,
              float* __restrict__ C, int M, int N, int sA,
              int mode, const float* __restrict__ bias, const float* __restrict__ dout,
              __nv_bfloat16* __restrict__ oAh, __nv_bfloat16* __restrict__ oAl, int sNext) {
    extern __shared__ __nv_bfloat16 dsm[];
    const uint32_t sbase = smem_u32(dsm);

    const int tid = threadIdx.x, lane = tid & 31, wid = tid >> 5;
    const int bm = blockIdx.y * 128, bn = blockIdx.x * 128;
    const int wm = (wid >> 1) * 32, wn = (wid & 1) * 64;
    const int nkt = sA >> 5;

    const int g = lane >> 3, l8 = lane & 7;
    const uint32_t aoff = (uint32_t)(((g & 1) * 8 + l8) * APAD + (g >> 1) * 8);
    const uint32_t boff = (uint32_t)(((g >> 1) * 8 + l8) * APAD + (g & 1) * 8);

    auto load_stage = [&](int kt, int st) {
        const int k0 = kt << 5;
        #pragma unroll
        for (int it = 0; it < 8; it++) {
            const int idx = it * 256 + tid;
            const int t = idx >> 9, rc = idx & 511;
            const int r = rc >> 2, c = rc & 3;
            const __nv_bfloat16* gsrc;
            if (t == 0)      gsrc = Ah + (size_t)(bm + r) * sA + k0 + c * 8;
            else if (t == 1) gsrc = Al + (size_t)(bm + r) * sA + k0 + c * 8;
            else if (t == 2) gsrc = Wh + (size_t)(bn + r) * sA + k0 + c * 8;
            else             gsrc = Wl + (size_t)(bn + r) * sA + k0 + c * 8;
            const uint32_t d = sbase + st * STAGE_B + t * TILE_B + r * 80 + c * 16;
            asm volatile("cp.async.ca.shared.global [%0], [%1], 16;" :: "r"(d), "l"(gsrc));
        }
    };

    float acc[2][8][4] = {};

    load_stage(0, 0);
    asm volatile("cp.async.commit_group;" ::: "memory");

    for (int kt = 0; kt < nkt; kt++) {
        const int st = kt & 1;
        if (kt + 1 < nkt) {
            load_stage(kt + 1, st ^ 1);
            asm volatile("cp.async.commit_group;" ::: "memory");
            asm volatile("cp.async.wait_group 1;" ::: "memory");
        } else {
            asm volatile("cp.async.wait_group 0;" ::: "memory");
        }
        __syncthreads();

        const uint32_t sAh_u = sbase + st * STAGE_B;
        const uint32_t sAl_u = sAh_u + TILE_B;
        const uint32_t sBh_u = sAh_u + 2 * TILE_B;
        const uint32_t sBl_u = sAh_u + 3 * TILE_B;

        #pragma unroll
        for (int ks = 0; ks < 2; ks++) {
            uint32_t ah[2][4], al[2][4];
            #pragma unroll
            for (int mb = 0; mb < 2; mb++) {
                const uint32_t off = (aoff + (uint32_t)(wm + mb * 16) * APAD + ks * 16) * 2;
                ldm_x4(ah[mb][0], ah[mb][1], ah[mb][2], ah[mb][3], sAh_u + off);
                ldm_x4(al[mb][0], al[mb][1], al[mb][2], al[mb][3], sAl_u + off);
            }
            #pragma unroll
            for (int nbp = 0; nbp < 4; nbp++) {
                const uint32_t off = (boff + (uint32_t)(wn + nbp * 16) * APAD + ks * 16) * 2;
                uint32_t bh[4], bl[4];
                ldm_x4(bh[0], bh[1], bh[2], bh[3], sBh_u + off);
                ldm_x4(bl[0], bl[1], bl[2], bl[3], sBl_u + off);
                #pragma unroll
                for (int h = 0; h < 2; h++) {
                    #pragma unroll
                    for (int mb = 0; mb < 2; mb++) {
                        float* d = acc[mb][nbp * 2 + h];
                        mma_bf16(d, ah[mb], bh + h * 2);
                        mma_bf16(d, ah[mb], bl + h * 2);
                        mma_bf16(d, al[mb], bh + h * 2);
                    }
                }
            }
        }
        __syncthreads();
    }

    const int mrow = lane >> 2, ncol = (lane & 3) * 2;
    #pragma unroll
    for (int mb = 0; mb < 2; mb++) {
        const int m0 = bm + wm + mb * 16 + mrow;
        float dv0 = 0.f, dv1 = 0.f;
        if (mode == 1) {
            if (m0 < M) dv0 = dout[m0];
            if (m0 + 8 < M) dv1 = dout[m0 + 8];
        }
        #pragma unroll
        for (int nb = 0; nb < 8; nb++) {
            const float* d = acc[mb][nb];
            const int n = bn + wn + nb * 8 + ncol;
            if (mode == 0) {
                if (m0 < M)
                    *reinterpret_cast<float2*>(C + (size_t)m0 * N + n) = make_float2(d[0], d[1]);
                if (m0 + 8 < M)
                    *reinterpret_cast<float2*>(C + (size_t)(m0 + 8) * N + n) = make_float2(d[2], d[3]);
            } else if (mode == 2) {
                const float b0 = bias[n], b1 = bias[n + 1];
                if (m0 < M)
                    *reinterpret_cast<float2*>(C + (size_t)m0 * N + n) = make_float2(d[0] + b0, d[1] + b1);
                if (m0 + 8 < M)
                    *reinterpret_cast<float2*>(C + (size_t)(m0 + 8) * N + n) = make_float2(d[2] + b0, d[3] + b1);
            } else {
                const float b0 = bias[n], b1 = bias[n + 1];
                if (m0 < M) {
                    float v0 = d[0] + b0, v1 = d[1] + b1;
                    v0 = ((v0 < 0.f) ? 0.01f * v0 : v0) * dv0;
                    v1 = ((v1 < 0.f) ? 0.01f * v1 : v1) * dv0;
                    uint32_t hi, lo; split2(v0, v1, hi, lo);
                    *reinterpret_cast<uint32_t*>(oAh + (size_t)m0 * sNext + n) = hi;
                    *reinterpret_cast<uint32_t*>(oAl + (size_t)m0 * sNext + n) = lo;
                }
                if (m0 + 8 < M) {
                    float v0 = d[2] + b0, v1 = d[3] + b1;
                    v0 = ((v0 < 0.f) ? 0.01f * v0 : v0) * dv1;
                    v1 = ((v1 < 0.f) ? 0.01f * v1 : v1) * dv1;
                    uint32_t hi, lo; split2(v0, v1, hi, lo);
                    *reinterpret_cast<uint32_t*>(oAh + (size_t)(m0 + 8) * sNext + n) = hi;
                    *reinterpret_cast<uint32_t*>(oAl + (size_t)(m0 + 8) * sNext + n) = lo;
                }
            }
        }
    }
}

// ================= fused W prep: all 5 layers in one launch =================
__global__ void prep_w_all(const float* __restrict__ W0, const float* __restrict__ W1,
                           const float* __restrict__ W2, const float* __restrict__ W3,
                           const float* __restrict__ W4,
                           __nv_bfloat16* __restrict__ Wh, __nv_bfloat16* __restrict__ Wl) {
    const int starts[6] = {0, 163840, 425984, 491520, 507904, 638976};
    const int Ks[5]     = {300, 1024, 512, 256, 128};
    const int Ns[5]     = {1024, 512, 256, 128, 2048};
    const int Kpads[5]  = {320, 1024, 512, 256, 128};
    const int woffs[5]  = {WOFF0, WOFF1, WOFF2, WOFF3, WOFF4};
    const float* Ws[5]  = {W0, W1, W2, W3, W4};

    int idx = blockIdx.x * blockDim.x + threadIdx.x;
    int stride = gridDim.x * blockDim.x;
    for (; idx < 638976; idx += stride) {
        int l = 0;
        #pragma unroll
        for (int q = 1; q < 5; q++) if (idx >= starts[q]) l = q;
        const int p = idx - starts[l];
        const int Kp2 = Kpads[l] >> 1;
        const int n = p / Kp2, pk = p - n * Kp2;
        const int k = pk * 2;
        const int K = Ks[l], N = Ns[l];
        float w0 = 0.f, w1 = 0.f;
        if (k < K)     w0 = Ws[l][(size_t)k * N + n];
        if (k + 1 < K) w1 = Ws[l][(size_t)(k + 1) * N + n];
        uint32_t hi, lo; split2(w0, w1, hi, lo);
        ((uint32_t*)(Wh + woffs[l]))[p] = hi;
        ((uint32_t*)(Wl + woffs[l]))[p] = lo;
    }
}

// ================= CSC build (parallel scan, 3 launches) =================
__global__ void hist_kernel(const int* __restrict__ src, const int* __restrict__ dst,
                            int* __restrict__ odeg, int* __restrict__ ideg, int nE) {
    int e = blockIdx.x * blockDim.x + threadIdx.x;
    if (e >= nE) return;
    int s = src[e], d = dst[e];
    if ((unsigned)s < N_NODES) atomicAdd(&odeg[s], 1);
    if ((unsigned)d < N_NODES) atomicAdd(&ideg[d], 1);
}

#define SCAN_BS 512
#define SCAN_NB ((N_NODES + SCAN_BS - 1) / SCAN_BS)  // 98

__global__ void blocksum_kernel(const int* __restrict__ deg, int* __restrict__ bsum) {
    __shared__ int sh[SCAN_BS];
    int i = blockIdx.x * SCAN_BS + threadIdx.x;
    sh[threadIdx.x] = (i < N_NODES) ? deg[i] : 0;
    __syncthreads();
    for (int s = SCAN_BS / 2; s > 0; s >>= 1) {
        if (threadIdx.x < s) sh[threadIdx.x] += sh[threadIdx.x + s];
        __syncthreads();
    }
    if (threadIdx.x == 0) bsum[blockIdx.x] = sh[0];
}

__global__ void scanpart_kernel(int* __restrict__ bsum, int nb) {
    __shared__ int sh[256];
    int t = threadIdx.x;
    int v = (t < nb) ? bsum[t] : 0;
    sh[t] = v;
    __syncthreads();
    for (int s = 1; s < 256; s <<= 1) {
        int add = (t >= s) ? sh[t - s] : 0;
        __syncthreads();
        sh[t] += add;
        __syncthreads();
    }
    if (t < nb) bsum[t] = sh[t] - v;  // exclusive
}

// offsets + dinv fused
__global__ void offsets_dinv_kernel(const int* __restrict__ ideg, const int* __restrict__ odeg,
                                    const int* __restrict__ bsum,
                                    int* __restrict__ off, int* __restrict__ cur,
                                    float* __restrict__ dout, float* __restrict__ din) {
    __shared__ int sh[SCAN_BS];
    int t = threadIdx.x;
    int i = blockIdx.x * SCAN_BS + t;
    int v = (i < N_NODES) ? ideg[i] : 0;
    if (i < N_NODES) {
        dout[i] = rsqrtf(fmaxf((float)odeg[i], 1.0f));
        din[i]  = rsqrtf(fmaxf((float)v, 1.0f));
    }
    sh[t] = v;
    __syncthreads();
    for (int s = 1; s < SCAN_BS; s <<= 1) {
        int add = (t >= s) ? sh[t - s] : 0;
        __syncthreads();
        sh[t] += add;
        __syncthreads();
    }
    if (i < N_NODES) {
        int excl = sh[t] - v + bsum[blockIdx.x];
        off[i] = excl;
        cur[i] = excl;
        if (i == N_NODES - 1) off[N_NODES] = excl + v;
    }
}

__global__ void fill_kernel(const int* __restrict__ src, const int* __restrict__ dst,
                            int* __restrict__ cur, int* __restrict__ csc, int nE) {
    int e = blockIdx.x * blockDim.x + threadIdx.x;
    if (e >= nE) return;
    int s = src[e], d = dst[e];
    if ((unsigned)s >= N_NODES || (unsigned)d >= N_NODES) return;
    int pos = atomicAdd(&cur[d], 1);
    csc[pos] = s;
}

// restore degree arrays for next replay (runs LAST)
__global__ void cleanup_kernel(int* __restrict__ ideg, int* __restrict__ odeg) {
    int i = blockIdx.x * blockDim.x + threadIdx.x;
    if (i < N_NODES) { ideg[i] = 0; odeg[i] = 0; }
}

// ================= gather_pre: u = dinv_in ⊙ S (opt dout ⊙) y  -> split bf16 =================
__global__ __launch_bounds__(256)
void gather_pre(const float* __restrict__ y, const float* __restrict__ dout,
                const int* __restrict__ off, const int* __restrict__ csc,
                int K4, int Kpad4,
                __nv_bfloat16* __restrict__ Ah, __nv_bfloat16* __restrict__ Al, int sNext,
                const float* __restrict__ dinv_in) {
    const int node = blockIdx.x * 8 + (threadIdx.x >> 5);
    if (node >= N_NODES) return;
    const int lane = threadIdx.x & 31;
    const int beg = off[node], end = off[node + 1];
    const float di = dinv_in[node];
    const float4* y4 = (const float4*)y;

    for (int c = lane; c < Kpad4; c += 32) {
        float4 acc = make_float4(0.f, 0.f, 0.f, 0.f);
        if (c < K4) {
            for (int j = beg; j < end; j++) {
                const int s = csc[j];
                float4 v = y4[(size_t)s * K4 + c];
                const float sc = dout ? dout[s] : 1.0f;
                acc.x += v.x * sc; acc.y += v.y * sc; acc.z += v.z * sc; acc.w += v.w * sc;
            }
        }
        uint32_t h0, l0, h1, l1;
        split2(acc.x * di, acc.y * di, h0, l0);
        split2(acc.z * di, acc.w * di, h1, l1);
        const size_t eo = (size_t)node * sNext + c * 4;
        *reinterpret_cast<uint2*>(Ah + eo) = make_uint2(h0, h1);
        *reinterpret_cast<uint2*>(Al + eo) = make_uint2(l0, l1);
    }
}

// ================= gather_post: agg = S t; act = leaky(dinv_in⊙agg + b) ⊙ dinv_out =================
__global__ __launch_bounds__(256)
void gather_post(const float* __restrict__ t, const int* __restrict__ off,
                 const int* __restrict__ csc, int N4, int cpn,
                 __nv_bfloat16* __restrict__ Ah, __nv_bfloat16* __restrict__ Al, int sNext,
                 const float* __restrict__ bias, const float* __restrict__ dinv_in,
                 const float* __restrict__ dinv_out, float* __restrict__ outF) {
    const int gw = blockIdx.x * 8 + (threadIdx.x >> 5);
    const int lane = threadIdx.x & 31;
    const int node = gw / cpn, chunk = gw - node * cpn;
    if (node >= N_NODES) return;
    const int c = chunk * 32 + lane;

    const float4* t4 = (const float4*)t;
    const int beg = off[node], end = off[node + 1];
    float4 acc = make_float4(0.f, 0.f, 0.f, 0.f);
    for (int j = beg; j < end; j++) {
        const int s = csc[j];
        float4 v = t4[(size_t)s * N4 + c];
        acc.x += v.x; acc.y += v.y; acc.z += v.z; acc.w += v.w;
    }
    const float di = dinv_in[node];
    const float dv = dinv_out[node];
    const float4 b = ((const float4*)bias)[c];
    float v0 = fmaf(acc.x, di, b.x);
    float v1 = fmaf(acc.y, di, b.y);
    float v2 = fmaf(acc.z, di, b.z);
    float v3 = fmaf(acc.w, di, b.w);
    v0 = ((v0 < 0.f) ? 0.01f * v0 : v0) * dv;
    v1 = ((v1 < 0.f) ? 0.01f * v1 : v1) * dv;
    v2 = ((v2 < 0.f) ? 0.01f * v2 : v2) * dv;
    v3 = ((v3 < 0.f) ? 0.01f * v3 : v3) * dv;

    if (outF) {
        ((float4*)outF)[(size_t)node * N4 + c] = make_float4(v0, v1, v2, v3);
    } else {
        uint32_t h0, l0, h1, l1;
        split2(v0, v1, h0, l0);
        split2(v2, v3, h1, l1);
        const size_t eo = (size_t)node * sNext + c * 4;
        *reinterpret_cast<uint2*>(Ah + eo) = make_uint2(h0, h1);
        *reinterpret_cast<uint2*>(Al + eo) = make_uint2(l0, l1);
    }
}

// ================= launch =================
extern "C" void kernel_launch(void* const* d_in, const int* in_sizes, int n_in,
                              void* d_out, int out_size) {
    const float* x = (const float*)d_in[0];
    const int* ei = (const int*)d_in[1];   // int32 (JAX x64 disabled)
    const float* W[5] = {(const float*)d_in[2], (const float*)d_in[4], (const float*)d_in[6],
                         (const float*)d_in[8], (const float*)d_in[10]};
    const float* B[5] = {(const float*)d_in[3], (const float*)d_in[5], (const float*)d_in[7],
                         (const float*)d_in[9], (const float*)d_in[11]};

    const int M = N_NODES;
    const int nE = N_EDGES;
    const int* src = ei;
    const int* dstp = ei + nE;

    float *tP, *yP, *doutP, *dinP;
    __nv_bfloat16 *Ah0, *Al0, *Ah1, *Al1, *WhP, *WlP;
    int *idegP, *odegP, *offP, *curP, *cscP, *bsumP;
    cudaGetSymbolAddress((void**)&tP, g_t);
    cudaGetSymbolAddress((void**)&yP, g_y);
    cudaGetSymbolAddress((void**)&Ah0, g_Ah0);
    cudaGetSymbolAddress((void**)&Al0, g_Al0);
    cudaGetSymbolAddress((void**)&Ah1, g_Ah1);
    cudaGetSymbolAddress((void**)&Al1, g_Al1);
    cudaGetSymbolAddress((void**)&WhP, g_Wh);
    cudaGetSymbolAddress((void**)&WlP, g_Wl);
    cudaGetSymbolAddress((void**)&doutP, g_dinv_out);
    cudaGetSymbolAddress((void**)&dinP, g_dinv_in);
    cudaGetSymbolAddress((void**)&idegP, g_ideg);
    cudaGetSymbolAddress((void**)&odegP, g_odeg);
    cudaGetSymbolAddress((void**)&offP, g_off);
    cudaGetSymbolAddress((void**)&curP, g_cur);
    cudaGetSymbolAddress((void**)&cscP, g_csc);
    cudaGetSymbolAddress((void**)&bsumP, g_bsum);

    cudaFuncSetAttribute(gemm_mma, cudaFuncAttributeMaxDynamicSharedMemorySize, SMEM_TOTAL_B);

    // degrees + parallel scan + CSC fill
    hist_kernel<<<(nE + 255) / 256, 256>>>(src, dstp, odegP, idegP, nE);
    blocksum_kernel<<<SCAN_NB, SCAN_BS>>>(idegP, bsumP);
    scanpart_kernel<<<1, 256>>>(bsumP, SCAN_NB);
    offsets_dinv_kernel<<<SCAN_NB, SCAN_BS>>>(idegP, odegP, bsumP, offP, curP, doutP, dinP);
    fill_kernel<<<(nE + 255) / 256, 256>>>(src, dstp, curP, cscP, nE);
    // layer-1 pre-aggregation (K=300 -> split A0, stride 320)
    gather_pre<<<(M + 7) / 8, 256>>>(x, doutP, offP, cscP, 75, 80, Ah0, Al0, 320, dinP);
    // all weight planes
    prep_w_all<<<640, 256>>>(W[0], W[1], W[2], W[3], W[4], WhP, WlP);

    // Layer 1 GEMM (K=320, N=1024) epilogue -> split A1
    {
        dim3 grid(1024 / 128, M_PAD / 128);
        gemm_mma<<<grid, 256, SMEM_TOTAL_B>>>(Ah0, Al0, WhP + WOFF0, WlP + WOFF0, nullptr,
                                              M, 1024, 320, 1, B[0], doutP, Ah1, Al1, 1024);
    }
    // Layer 2 (K=1024, N=512)
    {
        dim3 grid(512 / 128, M_PAD / 128);
        gemm_mma<<<grid, 256, SMEM_TOTAL_B>>>(Ah1, Al1, WhP + WOFF1, WlP + WOFF1, tP,
                                              M, 512, 1024, 0, nullptr, nullptr, nullptr, nullptr, 0);
    }
    gather_post<<<(M * 4 + 7) / 8, 256>>>(tP, offP, cscP, 128, 4, Ah0, Al0, 512,
                                          B[1], dinP, doutP, nullptr);
    // Layer 3 (K=512, N=256)
    {
        dim3 grid(256 / 128, M_PAD / 128);
        gemm_mma<<<grid, 256, SMEM_TOTAL_B>>>(Ah0, Al0, WhP + WOFF2, WlP + WOFF2, tP,
                                              M, 256, 512, 0, nullptr, nullptr, nullptr, nullptr, 0);
    }
    gather_post<<<(M * 2 + 7) / 8, 256>>>(tP, offP, cscP, 64, 2, Ah1, Al1, 256,
                                          B[2], dinP, doutP, nullptr);
    // Layer 4 (K=256, N=128) -> fp32 y
    {
        dim3 grid(128 / 128, M_PAD / 128);
        gemm_mma<<<grid, 256, SMEM_TOTAL_B>>>(Ah1, Al1, WhP + WOFF3, WlP + WOFF3, tP,
                                              M, 128, 256, 0, nullptr, nullptr, nullptr, nullptr, 0);
    }
    gather_post<<<(M + 7) / 8, 256>>>(tP, offP, cscP, 32, 1, nullptr, nullptr, 0,
                                      B[3], dinP, doutP, yP);
    // Layer 5 (aggregate-first, K=128, N=2048) -> d_out
    gather_pre<<<(M + 7) / 8, 256>>>(yP, nullptr, offP, cscP, 32, 32, Ah0, Al0, 128, dinP);
    {
        dim3 grid(2048 / 128, M_PAD / 128);
        gemm_mma<<<grid, 256, SMEM_TOTAL_B>>>(Ah0, Al0, WhP + WOFF4, WlP + WOFF4, (float*)d_out,
                                              M, 2048, 128, 2, B[4], nullptr, nullptr, nullptr, 0);
    }
    // restore degree arrays for next replay
    cleanup_kernel<<<(M + 255) / 256, 256>>>(idegP, odegP);
}